// round 4
// baseline (speedup 1.0000x reference)
#include <cuda_runtime.h>
#include <cuda_fp16.h>
#include <math.h>

// Problem constants (static in the reference)
#define EMBED   256
#define HEADS   8
#define LEVELS  3
#define POINTS  4
#define DHEAD   32
#define BATCH   2
#define SEQ     21504          // 128*128 + 64*64 + 32*32
#define NQUERY  21504
#define MROWS   (BATCH * NQUERY)   // 43008

// Scratch (device globals; no allocation allowed)
__device__ uint4 g_value_h4[(size_t)BATCH * SEQ * EMBED / 8];            // fp16 [B,S,H,D]
__device__ float g_off  [(size_t)MROWS * HEADS * LEVELS * POINTS * 2];   // [B*Q,192]
__device__ float g_aw   [(size_t)MROWS * HEADS * LEVELS * POINTS];       // [B*Q,96]
__device__ float g_msda [(size_t)MROWS * EMBED];                         // [B*Q,256]

__device__ __forceinline__ unsigned f2tf32(float f) {
    unsigned u;
    asm("cvt.rna.tf32.f32 %0, %1;" : "=r"(u) : "f"(f));
    return u;
}

__device__ __forceinline__ void cp_async16(unsigned smem_addr, const void* gptr, int src_size) {
    asm volatile("cp.async.cg.shared.global [%0], [%1], 16, %2;\n"
                 :: "r"(smem_addr), "l"(gptr), "r"(src_size));
}
__device__ __forceinline__ void cp_async_commit() {
    asm volatile("cp.async.commit_group;\n");
}

// ---------------------------------------------------------------------------
// TF32 tensor-core GEMM: C[M,N] = A[M,256] * W[N,256]^T + bias[N]
// BM=128, BN=128, BK=32; 256 threads = 8 warps (4 m x 2 n), warp tile 32x64.
// Double-buffered cp.async; XOR-swizzled smem. 64KB dynamic smem.
// If Ch != nullptr, write __half output instead of float.
// ---------------------------------------------------------------------------
extern __shared__ float4 smem_dyn[];

__global__ void __launch_bounds__(256) mma_gemm_wt_bias(
    const float* __restrict__ A, const float* __restrict__ W,
    const float* __restrict__ bias, float* __restrict__ C,
    __half* __restrict__ Ch, int N)
{
    const int K = 256;
    // layout: [stage][A 1024 | W 1024] float4 chunks
    float4* As4[2] = { smem_dyn,            smem_dyn + 2048 };
    float4* Ws4[2] = { smem_dyn + 1024,     smem_dyn + 3072 };

    const int tid  = threadIdx.x;
    const int wid  = tid >> 5;
    const int lane = tid & 31;
    const int g    = lane >> 2;     // 0..7
    const int t    = lane & 3;      // 0..3

    const int m0 = blockIdx.y * 128;
    const int n0 = blockIdx.x * 128;
    const int warp_m = (wid & 3) * 32;
    const int warp_n = (wid >> 2) * 64;

    const int a_row0 = tid >> 3;          // 0..31 (+32 per rep)
    const int a_c    = tid & 7;

    float acc[2][8][4];
#pragma unroll
    for (int mi = 0; mi < 2; mi++)
#pragma unroll
        for (int ni = 0; ni < 8; ni++)
#pragma unroll
            for (int c = 0; c < 4; c++) acc[mi][ni][c] = 0.f;

    auto load_stage = [&](int stage, int k0) {
#pragma unroll
        for (int i = 0; i < 4; i++) {
            int row = a_row0 + i * 32;
            int sw  = a_c ^ (row & 7);
            unsigned dst = (unsigned)__cvta_generic_to_shared(&As4[stage][row * 8 + sw]);
            cp_async16(dst, &A[(size_t)(m0 + row) * K + k0 + a_c * 4], 16);
        }
#pragma unroll
        for (int i = 0; i < 4; i++) {
            int row = a_row0 + i * 32;      // 0..127
            int sw  = a_c ^ (row & 7);
            unsigned dst = (unsigned)__cvta_generic_to_shared(&Ws4[stage][row * 8 + sw]);
            int n  = n0 + row;
            int ok = (n < N) ? 16 : 0;
            const float* src = (n < N) ? &W[(size_t)n * K + k0 + a_c * 4] : W;
            cp_async16(dst, src, ok);
        }
        cp_async_commit();
    };

    load_stage(0, 0);

    const int NIT = K / 32;   // 8
#pragma unroll 1
    for (int it = 0; it < NIT; it++) {
        const int cur = it & 1;
        if (it + 1 < NIT) {
            load_stage(cur ^ 1, (it + 1) * 32);
            asm volatile("cp.async.wait_group 1;\n");
        } else {
            asm volatile("cp.async.wait_group 0;\n");
        }
        __syncthreads();

        const float* Af = (const float*)As4[cur];
        const float* Wf = (const float*)Ws4[cur];
#pragma unroll
        for (int kk = 0; kk < 4; kk++) {
            const int c0 = kk * 2;
            const int c1 = c0 + 1;
            unsigned a[2][4], b[8][2];
#pragma unroll
            for (int mi = 0; mi < 2; mi++) {
                int r0 = warp_m + mi * 16 + g;
                int r1 = r0 + 8;
                a[mi][0] = f2tf32(Af[r0 * 32 + ((c0 ^ (r0 & 7)) << 2) + t]);
                a[mi][1] = f2tf32(Af[r1 * 32 + ((c0 ^ (r1 & 7)) << 2) + t]);
                a[mi][2] = f2tf32(Af[r0 * 32 + ((c1 ^ (r0 & 7)) << 2) + t]);
                a[mi][3] = f2tf32(Af[r1 * 32 + ((c1 ^ (r1 & 7)) << 2) + t]);
            }
#pragma unroll
            for (int ni = 0; ni < 8; ni++) {
                int rn = warp_n + ni * 8 + g;
                b[ni][0] = f2tf32(Wf[rn * 32 + ((c0 ^ (rn & 7)) << 2) + t]);
                b[ni][1] = f2tf32(Wf[rn * 32 + ((c1 ^ (rn & 7)) << 2) + t]);
            }
#pragma unroll
            for (int mi = 0; mi < 2; mi++)
#pragma unroll
                for (int ni = 0; ni < 8; ni++) {
                    asm volatile(
                        "mma.sync.aligned.m16n8k8.row.col.f32.tf32.tf32.f32 "
                        "{%0,%1,%2,%3}, {%4,%5,%6,%7}, {%8,%9}, {%0,%1,%2,%3};"
                        : "+f"(acc[mi][ni][0]), "+f"(acc[mi][ni][1]),
                          "+f"(acc[mi][ni][2]), "+f"(acc[mi][ni][3])
                        : "r"(a[mi][0]), "r"(a[mi][1]), "r"(a[mi][2]), "r"(a[mi][3]),
                          "r"(b[ni][0]), "r"(b[ni][1]));
                }
        }
        __syncthreads();
    }

    // epilogue
#pragma unroll
    for (int mi = 0; mi < 2; mi++) {
        int row0 = m0 + warp_m + mi * 16 + g;
#pragma unroll
        for (int ni = 0; ni < 8; ni++) {
            int col = n0 + warp_n + ni * 8 + t * 2;
            if (col < N) {
                float bx = bias[col], by = bias[col + 1];
                float v00 = acc[mi][ni][0] + bx, v01 = acc[mi][ni][1] + by;
                float v10 = acc[mi][ni][2] + bx, v11 = acc[mi][ni][3] + by;
                if (Ch) {
                    *reinterpret_cast<__half2*>(&Ch[(size_t)row0 * N + col]) =
                        __floats2half2_rn(v00, v01);
                    *reinterpret_cast<__half2*>(&Ch[(size_t)(row0 + 8) * N + col]) =
                        __floats2half2_rn(v10, v11);
                } else {
                    *reinterpret_cast<float2*>(&C[(size_t)row0 * N + col]) =
                        make_float2(v00, v01);
                    *reinterpret_cast<float2*>(&C[(size_t)(row0 + 8) * N + col]) =
                        make_float2(v10, v11);
                }
            }
        }
    }
}

// ---------------------------------------------------------------------------
// Deformable sampling, two-phase per block. Value in fp16 [B,S,H,D].
// Block = 8 queries x 8 heads = 64 units; unit = 4 lanes x 8 channels (uint4).
// ---------------------------------------------------------------------------
#define QB 8
#define NSAMP (QB * HEADS * LEVELS * POINTS)   // 768

__global__ void __launch_bounds__(256) msda_sample_kernel(
    const float* __restrict__ refp)
{
    __shared__ float  s_aw[QB * HEADS * 12];
    __shared__ int4   s_off[NSAMP];            // 4 corner offsets (uint4 units)
    __shared__ float4 s_wt[NSAMP];             // premultiplied corner weights

    const int tid = threadIdx.x;
    const int bq0 = blockIdx.x * QB;

    // Phase 1a: softmax once per (q, h)
    if (tid < QB * HEADS) {
        const int bqi = tid >> 3;
        const int h   = tid & 7;
        const float* awp = g_aw + (size_t)(bq0 + bqi) * 96 + h * 12;
        float w[12];
        float mx = -1e30f;
#pragma unroll
        for (int j = 0; j < 12; j++) { w[j] = awp[j]; mx = fmaxf(mx, w[j]); }
        float s = 0.f;
#pragma unroll
        for (int j = 0; j < 12; j++) { w[j] = __expf(w[j] - mx); s += w[j]; }
        const float invs = 1.f / s;
#pragma unroll
        for (int j = 0; j < 12; j++) s_aw[tid * 12 + j] = w[j] * invs;
    }
    __syncthreads();

    // Phase 1b: per-sample params (3 samples per thread)
    const int lvlW[3]     = {128, 64, 32};
    const int lvlStart[3] = {0, 16384, 20480};
#pragma unroll
    for (int i = 0; i < 3; i++) {
        const int sid = tid + i * 256;         // 0..767
        const int bqi = sid / 96;
        const int r   = sid - bqi * 96;
        const int h   = r / 12;
        const int lp  = r - h * 12;
        const int l   = lp >> 2;

        const int bq = bq0 + bqi;
        const int b  = (bq >= NQUERY) ? 1 : 0;
        const int Wl = lvlW[l];
        const float fW = (float)Wl;

        const float ox = g_off[(size_t)bq * 192 + h * 24 + lp * 2 + 0];
        const float oy = g_off[(size_t)bq * 192 + h * 24 + lp * 2 + 1];
        const float rx = refp[(size_t)bq * 6 + l * 2 + 0];
        const float ry = refp[(size_t)bq * 6 + l * 2 + 1];

        const float x = fmaf(rx, fW, ox) - 0.5f;
        const float y = fmaf(ry, fW, oy) - 0.5f;
        const float xf = floorf(x), yf = floorf(y);
        const float wx = x - xf,    wy = y - yf;
        const int x0 = (int)xf, y0 = (int)yf;

        const bool vx0 = (x0 >= 0)  && (x0 < Wl);
        const bool vx1 = (x0 >= -1) && (x0 < Wl - 1);
        const bool vy0 = (y0 >= 0)  && (y0 < Wl);
        const bool vy1 = (y0 >= -1) && (y0 < Wl - 1);

        const int x0c = min(max(x0, 0), Wl - 1);
        const int x1c = min(max(x0 + 1, 0), Wl - 1);
        const int y0c = min(max(y0, 0), Wl - 1);
        const int y1c = min(max(y0 + 1, 0), Wl - 1);

        const float ws = s_aw[(bqi * 8 + h) * 12 + lp];
        float4 wt;
        wt.x = (vx0 && vy0) ? ws * (1.f - wx) * (1.f - wy) : 0.f;
        wt.y = (vx1 && vy0) ? ws *        wx  * (1.f - wy) : 0.f;
        wt.z = (vx0 && vy1) ? ws * (1.f - wx) *        wy  : 0.f;
        wt.w = (vx1 && vy1) ? ws *        wx  *        wy  : 0.f;

        // base in uint4 units: pixel stride = 32, head stride = 4
        const int base = ((b * SEQ + lvlStart[l]) * 8 + h) * 4;
        int4 off;
        off.x = base + (y0c * Wl + x0c) * 32;
        off.y = base + (y0c * Wl + x1c) * 32;
        off.z = base + (y1c * Wl + x0c) * 32;
        off.w = base + (y1c * Wl + x1c) * 32;

        s_off[sid] = off;
        s_wt[sid]  = wt;
    }
    __syncthreads();

    // Phase 2: gather. 64 units x 4 lanes; lane holds 8 channels (uint4 fp16).
    const uint4* __restrict__ V = g_value_h4;
    const int cg  = tid & 3;
    const int u   = tid >> 2;       // 0..63
    const int bqi = u >> 3;
    const int h   = u & 7;

    float acc[8];
#pragma unroll
    for (int c = 0; c < 8; c++) acc[c] = 0.f;

#pragma unroll
    for (int s12 = 0; s12 < 12; s12++) {
        const int sid = u * 12 + s12;
        const int4   off = s_off[sid];
        const float4 wt  = s_wt[sid];
        uint4 r00 = V[off.x + cg];
        uint4 r01 = V[off.y + cg];
        uint4 r10 = V[off.z + cg];
        uint4 r11 = V[off.w + cg];
        const __half2* h00 = reinterpret_cast<const __half2*>(&r00);
        const __half2* h01 = reinterpret_cast<const __half2*>(&r01);
        const __half2* h10 = reinterpret_cast<const __half2*>(&r10);
        const __half2* h11 = reinterpret_cast<const __half2*>(&r11);
#pragma unroll
        for (int j = 0; j < 4; j++) {
            float2 f00 = __half22float2(h00[j]);
            float2 f01 = __half22float2(h01[j]);
            float2 f10 = __half22float2(h10[j]);
            float2 f11 = __half22float2(h11[j]);
            acc[2*j]   = fmaf(wt.x, f00.x, fmaf(wt.y, f01.x, fmaf(wt.z, f10.x, fmaf(wt.w, f11.x, acc[2*j]))));
            acc[2*j+1] = fmaf(wt.x, f00.y, fmaf(wt.y, f01.y, fmaf(wt.z, f10.y, fmaf(wt.w, f11.y, acc[2*j+1]))));
        }
    }

    // write 8 channels = 2 float4
    float4* outp = reinterpret_cast<float4*>(g_msda)
                 + ((size_t)(bq0 + bqi) * 8 + h) * 8 + cg * 2;
    outp[0] = make_float4(acc[0], acc[1], acc[2], acc[3]);
    outp[1] = make_float4(acc[4], acc[5], acc[6], acc[7]);
}

// ---------------------------------------------------------------------------

extern "C" void kernel_launch(void* const* d_in, const int* in_sizes, int n_in,
                              void* d_out, int out_size)
{
    const float* hidden = (const float*)d_in[0];   // [B,Q,256]
    const float* enc    = (const float*)d_in[1];   // [B,S,256]
    const float* refp   = (const float*)d_in[2];   // [B,Q,L,2]
    // d_in[3] = spatial_shapes (static, hardcoded)
    const float* off_w  = (const float*)d_in[4];   // [192,256]
    const float* off_b  = (const float*)d_in[5];
    const float* aw_w   = (const float*)d_in[6];   // [96,256]
    const float* aw_b   = (const float*)d_in[7];
    const float* val_w  = (const float*)d_in[8];   // [256,256]
    const float* val_b  = (const float*)d_in[9];
    const float* out_w  = (const float*)d_in[10];  // [256,256]
    const float* out_b  = (const float*)d_in[11];
    float* out = (float*)d_out;

    float *p_off, *p_aw, *p_msda;
    __half* p_valh;
    cudaGetSymbolAddress((void**)&p_valh, g_value_h4);
    cudaGetSymbolAddress((void**)&p_off,  g_off);
    cudaGetSymbolAddress((void**)&p_aw,   g_aw);
    cudaGetSymbolAddress((void**)&p_msda, g_msda);

    static int smem_set = 0;
    const int SMEM_BYTES = 65536;
    if (!smem_set) {
        cudaFuncSetAttribute(mma_gemm_wt_bias,
                             cudaFuncAttributeMaxDynamicSharedMemorySize, SMEM_BYTES);
        smem_set = 1;
    }

    const int MB = MROWS / 128;   // 336
    dim3 blk(256);

    // value projection -> fp16 [B,S,H,D]
    mma_gemm_wt_bias<<<dim3(2, MB), blk, SMEM_BYTES>>>(enc, val_w, val_b, nullptr, p_valh, 256);
    // sampling offsets: N=192
    mma_gemm_wt_bias<<<dim3(2, MB), blk, SMEM_BYTES>>>(hidden, off_w, off_b, p_off, nullptr, 192);
    // attention weights: N=96
    mma_gemm_wt_bias<<<dim3(1, MB), blk, SMEM_BYTES>>>(hidden, aw_w, aw_b, p_aw, nullptr, 96);

    // deformable sampling: block = 8 queries x 8 heads
    msda_sample_kernel<<<MROWS / QB, blk>>>(refp);

    // output projection
    mma_gemm_wt_bias<<<dim3(2, MB), blk, SMEM_BYTES>>>(p_msda, out_w, out_b, out, nullptr, 256);
}

// round 5
// speedup vs baseline: 1.7458x; 1.7458x over previous
#include <cuda_runtime.h>
#include <cuda_fp16.h>
#include <math.h>

// Problem constants (static in the reference)
#define EMBED   256
#define HEADS   8
#define LEVELS  3
#define POINTS  4
#define DHEAD   32
#define BATCH   2
#define SEQ     21504          // 128*128 + 64*64 + 32*32
#define NQUERY  21504
#define MROWS   (BATCH * NQUERY)   // 43008

// Scratch (device globals; no allocation allowed)
__device__ uint4  g_value_h4[(size_t)BATCH * SEQ * EMBED / 8];   // fp16 value [B,S,H,D]
__device__ __half g_hidden_h[(size_t)MROWS * EMBED];
__device__ __half g_enc_h   [(size_t)BATCH * SEQ * EMBED];
__device__ __half g_msda_h  [(size_t)MROWS * EMBED];
__device__ __half g_valw_h  [256 * 256];
__device__ __half g_offw_h  [192 * 256];
__device__ __half g_aww_h   [96 * 256];
__device__ __half g_outw_h  [256 * 256];
__device__ float  g_off [(size_t)MROWS * 192];
__device__ float  g_aw  [(size_t)MROWS * 96];

// ---------------------------------------------------------------------------
// fp32 -> fp16 conversion (8 elements / thread)
// ---------------------------------------------------------------------------
__global__ void f2h_kernel(const float4* __restrict__ src, uint4* __restrict__ dst, int n8)
{
    int i = blockIdx.x * blockDim.x + threadIdx.x;
    if (i >= n8) return;
    float4 f0 = src[2 * i];
    float4 f1 = src[2 * i + 1];
    __half2 h0 = __floats2half2_rn(f0.x, f0.y);
    __half2 h1 = __floats2half2_rn(f0.z, f0.w);
    __half2 h2 = __floats2half2_rn(f1.x, f1.y);
    __half2 h3 = __floats2half2_rn(f1.z, f1.w);
    uint4 o;
    o.x = *reinterpret_cast<unsigned*>(&h0);
    o.y = *reinterpret_cast<unsigned*>(&h1);
    o.z = *reinterpret_cast<unsigned*>(&h2);
    o.w = *reinterpret_cast<unsigned*>(&h3);
    dst[i] = o;
}

__device__ __forceinline__ void cp_async16(unsigned smem_addr, const void* gptr, int src_size) {
    asm volatile("cp.async.cg.shared.global [%0], [%1], 16, %2;\n"
                 :: "r"(smem_addr), "l"(gptr), "r"(src_size));
}
__device__ __forceinline__ void ldmatrix_x4(unsigned* r, unsigned addr) {
    asm volatile("ldmatrix.sync.aligned.m8n8.x4.shared.b16 {%0,%1,%2,%3}, [%4];"
                 : "=r"(r[0]), "=r"(r[1]), "=r"(r[2]), "=r"(r[3]) : "r"(addr));
}

// ---------------------------------------------------------------------------
// FP16 tensor-core GEMM: C[M,N] = A[M,256] * W[N,256]^T + bias[N]
// BM=128, BN=64, BK=64; 256 threads = 8 warps (4 m x 2 n), warp tile 32x32.
// ldmatrix fragment loads + mma.m16n8k16; double-buffered cp.async;
// 128B-row XOR swizzle (conflict-free). M multiple of 128, N guarded.
// ---------------------------------------------------------------------------
__global__ void __launch_bounds__(256) hgemm_wt_bias(
    const __half* __restrict__ A, const __half* __restrict__ W,
    const float* __restrict__ bias, float* __restrict__ C,
    __half* __restrict__ Ch, int N)
{
    const int K = 256;
    // per stage: A 128 rows x 128B = 16KB, W 64 rows x 128B = 8KB
    __shared__ __align__(16) char smem[2 * (16384 + 8192)];
    const unsigned smem_u = (unsigned)__cvta_generic_to_shared(smem);

    const int tid  = threadIdx.x;
    const int wid  = tid >> 5;
    const int lane = tid & 31;

    const int m0 = blockIdx.y * 128;
    const int n0 = blockIdx.x * 64;
    const int warp_m = (wid & 3) * 32;
    const int warp_n = (wid >> 2) * 32;

    const int s_row0 = tid >> 3;      // 0..31
    const int s_c    = tid & 7;

    float acc[2][4][4];
#pragma unroll
    for (int mi = 0; mi < 2; mi++)
#pragma unroll
        for (int ni = 0; ni < 4; ni++)
#pragma unroll
            for (int c = 0; c < 4; c++) acc[mi][ni][c] = 0.f;

    auto load_stage = [&](int stage, int k0) {
        const unsigned a_base = smem_u + stage * 24576;
        const unsigned w_base = a_base + 16384;
        // A: 128 rows x 8 chunks (16B = 8 halves each)
#pragma unroll
        for (int i = 0; i < 4; i++) {
            int row = s_row0 + i * 32;
            int sw  = s_c ^ (row & 7);
            cp_async16(a_base + (row * 8 + sw) * 16,
                       &A[(size_t)(m0 + row) * K + k0 + s_c * 8], 16);
        }
        // W: 64 rows x 8 chunks
#pragma unroll
        for (int i = 0; i < 2; i++) {
            int row = s_row0 + i * 32;   // 0..63
            int sw  = s_c ^ (row & 7);
            int n   = n0 + row;
            int ok  = (n < N) ? 16 : 0;
            const __half* src = (n < N) ? &W[(size_t)n * K + k0 + s_c * 8] : W;
            cp_async16(w_base + (row * 8 + sw) * 16, src, ok);
        }
        asm volatile("cp.async.commit_group;\n");
    };

    load_stage(0, 0);

    // ldmatrix lane-derived indices
    const int a_moff = (lane & 8) + (lane & 7);        // row within 16-group
    const int a_koff = (lane & 16) >> 1;               // 0 or 8 halves
    const int b_noff = ((lane & 16) >> 1) + (lane & 7);
    const int b_koff = lane & 8;

    const int NIT = K / 64;   // 4
#pragma unroll 1
    for (int it = 0; it < NIT; it++) {
        const int cur = it & 1;
        if (it + 1 < NIT) {
            load_stage(cur ^ 1, (it + 1) * 64);
            asm volatile("cp.async.wait_group 1;\n");
        } else {
            asm volatile("cp.async.wait_group 0;\n");
        }
        __syncthreads();

        const unsigned a_base = smem_u + cur * 24576;
        const unsigned w_base = a_base + 16384;

#pragma unroll
        for (int kk = 0; kk < 4; kk++) {
            unsigned a[2][4], b[2][4];
#pragma unroll
            for (int mi = 0; mi < 2; mi++) {
                int m_r = warp_m + mi * 16 + a_moff;
                int k_h = kk * 16 + a_koff;
                int sw  = (k_h >> 3) ^ (m_r & 7);
                ldmatrix_x4(a[mi], a_base + (m_r * 8 + sw) * 16);
            }
#pragma unroll
            for (int bi = 0; bi < 2; bi++) {
                int n_r = warp_n + bi * 16 + b_noff;
                int k_h = kk * 16 + b_koff;
                int sw  = (k_h >> 3) ^ (n_r & 7);
                ldmatrix_x4(b[bi], w_base + (n_r * 8 + sw) * 16);
            }
#pragma unroll
            for (int mi = 0; mi < 2; mi++)
#pragma unroll
                for (int ni = 0; ni < 4; ni++) {
                    unsigned b0 = b[ni >> 1][(ni & 1) * 2];
                    unsigned b1 = b[ni >> 1][(ni & 1) * 2 + 1];
                    asm volatile(
                        "mma.sync.aligned.m16n8k16.row.col.f32.f16.f16.f32 "
                        "{%0,%1,%2,%3}, {%4,%5,%6,%7}, {%8,%9}, {%0,%1,%2,%3};"
                        : "+f"(acc[mi][ni][0]), "+f"(acc[mi][ni][1]),
                          "+f"(acc[mi][ni][2]), "+f"(acc[mi][ni][3])
                        : "r"(a[mi][0]), "r"(a[mi][1]), "r"(a[mi][2]), "r"(a[mi][3]),
                          "r"(b0), "r"(b1));
                }
        }
        __syncthreads();
    }

    // epilogue
    const int g = lane >> 2;
    const int t = lane & 3;
#pragma unroll
    for (int mi = 0; mi < 2; mi++) {
        int row0 = m0 + warp_m + mi * 16 + g;
#pragma unroll
        for (int ni = 0; ni < 4; ni++) {
            int col = n0 + warp_n + ni * 8 + t * 2;
            if (col < N) {
                float bx = bias[col], by = bias[col + 1];
                float v00 = acc[mi][ni][0] + bx, v01 = acc[mi][ni][1] + by;
                float v10 = acc[mi][ni][2] + bx, v11 = acc[mi][ni][3] + by;
                if (Ch) {
                    *reinterpret_cast<__half2*>(&Ch[(size_t)row0 * N + col]) =
                        __floats2half2_rn(v00, v01);
                    *reinterpret_cast<__half2*>(&Ch[(size_t)(row0 + 8) * N + col]) =
                        __floats2half2_rn(v10, v11);
                } else {
                    *reinterpret_cast<float2*>(&C[(size_t)row0 * N + col]) =
                        make_float2(v00, v01);
                    *reinterpret_cast<float2*>(&C[(size_t)(row0 + 8) * N + col]) =
                        make_float2(v10, v11);
                }
            }
        }
    }
}

// ---------------------------------------------------------------------------
// Deformable sampling, two-phase per block. Value fp16 [B,S,H,D].
// Block = 8 queries x 8 heads = 64 units; unit = 4 lanes x 8 channels (uint4).
// Output written directly as fp16 for the output GEMM.
// ---------------------------------------------------------------------------
#define QB 8
#define NSAMP (QB * HEADS * LEVELS * POINTS)   // 768

__global__ void __launch_bounds__(256) msda_sample_kernel(
    const float* __restrict__ refp)
{
    __shared__ float  s_aw[QB * HEADS * 12];
    __shared__ int4   s_off[NSAMP];            // 4 corner offsets (uint4 units)
    __shared__ float4 s_wt[NSAMP];             // premultiplied corner weights

    const int tid = threadIdx.x;
    const int bq0 = blockIdx.x * QB;

    // Phase 1a: softmax once per (q, h)
    if (tid < QB * HEADS) {
        const int bqi = tid >> 3;
        const int h   = tid & 7;
        const float* awp = g_aw + (size_t)(bq0 + bqi) * 96 + h * 12;
        float w[12];
        float mx = -1e30f;
#pragma unroll
        for (int j = 0; j < 12; j++) { w[j] = awp[j]; mx = fmaxf(mx, w[j]); }
        float s = 0.f;
#pragma unroll
        for (int j = 0; j < 12; j++) { w[j] = __expf(w[j] - mx); s += w[j]; }
        const float invs = 1.f / s;
#pragma unroll
        for (int j = 0; j < 12; j++) s_aw[tid * 12 + j] = w[j] * invs;
    }
    __syncthreads();

    // Phase 1b: per-sample params (3 samples per thread)
    const int lvlW[3]     = {128, 64, 32};
    const int lvlStart[3] = {0, 16384, 20480};
#pragma unroll
    for (int i = 0; i < 3; i++) {
        const int sid = tid + i * 256;         // 0..767
        const int bqi = sid / 96;
        const int r   = sid - bqi * 96;
        const int h   = r / 12;
        const int lp  = r - h * 12;
        const int l   = lp >> 2;

        const int bq = bq0 + bqi;
        const int b  = (bq >= NQUERY) ? 1 : 0;
        const int Wl = lvlW[l];
        const float fW = (float)Wl;

        const float ox = g_off[(size_t)bq * 192 + h * 24 + lp * 2 + 0];
        const float oy = g_off[(size_t)bq * 192 + h * 24 + lp * 2 + 1];
        const float rx = refp[(size_t)bq * 6 + l * 2 + 0];
        const float ry = refp[(size_t)bq * 6 + l * 2 + 1];

        const float x = fmaf(rx, fW, ox) - 0.5f;
        const float y = fmaf(ry, fW, oy) - 0.5f;
        const float xf = floorf(x), yf = floorf(y);
        const float wx = x - xf,    wy = y - yf;
        const int x0 = (int)xf, y0 = (int)yf;

        const bool vx0 = (x0 >= 0)  && (x0 < Wl);
        const bool vx1 = (x0 >= -1) && (x0 < Wl - 1);
        const bool vy0 = (y0 >= 0)  && (y0 < Wl);
        const bool vy1 = (y0 >= -1) && (y0 < Wl - 1);

        const int x0c = min(max(x0, 0), Wl - 1);
        const int x1c = min(max(x0 + 1, 0), Wl - 1);
        const int y0c = min(max(y0, 0), Wl - 1);
        const int y1c = min(max(y0 + 1, 0), Wl - 1);

        const float ws = s_aw[(bqi * 8 + h) * 12 + lp];
        float4 wt;
        wt.x = (vx0 && vy0) ? ws * (1.f - wx) * (1.f - wy) : 0.f;
        wt.y = (vx1 && vy0) ? ws *        wx  * (1.f - wy) : 0.f;
        wt.z = (vx0 && vy1) ? ws * (1.f - wx) *        wy  : 0.f;
        wt.w = (vx1 && vy1) ? ws *        wx  *        wy  : 0.f;

        // base in uint4 units: pixel stride = 32, head stride = 4
        const int base = ((b * SEQ + lvlStart[l]) * 8 + h) * 4;
        int4 off;
        off.x = base + (y0c * Wl + x0c) * 32;
        off.y = base + (y0c * Wl + x1c) * 32;
        off.z = base + (y1c * Wl + x0c) * 32;
        off.w = base + (y1c * Wl + x1c) * 32;

        s_off[sid] = off;
        s_wt[sid]  = wt;
    }
    __syncthreads();

    // Phase 2: gather. 64 units x 4 lanes; lane holds 8 channels (uint4 fp16).
    const uint4* __restrict__ V = g_value_h4;
    const int cg  = tid & 3;
    const int u   = tid >> 2;       // 0..63
    const int bqi = u >> 3;
    const int h   = u & 7;

    float acc[8];
#pragma unroll
    for (int c = 0; c < 8; c++) acc[c] = 0.f;

#pragma unroll
    for (int s12 = 0; s12 < 12; s12++) {
        const int sid = u * 12 + s12;
        const int4   off = s_off[sid];
        const float4 wt  = s_wt[sid];
        uint4 r00 = V[off.x + cg];
        uint4 r01 = V[off.y + cg];
        uint4 r10 = V[off.z + cg];
        uint4 r11 = V[off.w + cg];
        const __half2* h00 = reinterpret_cast<const __half2*>(&r00);
        const __half2* h01 = reinterpret_cast<const __half2*>(&r01);
        const __half2* h10 = reinterpret_cast<const __half2*>(&r10);
        const __half2* h11 = reinterpret_cast<const __half2*>(&r11);
#pragma unroll
        for (int j = 0; j < 4; j++) {
            float2 f00 = __half22float2(h00[j]);
            float2 f01 = __half22float2(h01[j]);
            float2 f10 = __half22float2(h10[j]);
            float2 f11 = __half22float2(h11[j]);
            acc[2*j]   = fmaf(wt.x, f00.x, fmaf(wt.y, f01.x, fmaf(wt.z, f10.x, fmaf(wt.w, f11.x, acc[2*j]))));
            acc[2*j+1] = fmaf(wt.x, f00.y, fmaf(wt.y, f01.y, fmaf(wt.z, f10.y, fmaf(wt.w, f11.y, acc[2*j+1]))));
        }
    }

    // write 8 channels as fp16 (one STG.128)
    __half2 o0 = __floats2half2_rn(acc[0], acc[1]);
    __half2 o1 = __floats2half2_rn(acc[2], acc[3]);
    __half2 o2 = __floats2half2_rn(acc[4], acc[5]);
    __half2 o3 = __floats2half2_rn(acc[6], acc[7]);
    uint4 ov;
    ov.x = *reinterpret_cast<unsigned*>(&o0);
    ov.y = *reinterpret_cast<unsigned*>(&o1);
    ov.z = *reinterpret_cast<unsigned*>(&o2);
    ov.w = *reinterpret_cast<unsigned*>(&o3);
    uint4* outp = reinterpret_cast<uint4*>(g_msda_h)
                + (size_t)(bq0 + bqi) * 32 + h * 4 + cg;
    *outp = ov;
}

// ---------------------------------------------------------------------------

extern "C" void kernel_launch(void* const* d_in, const int* in_sizes, int n_in,
                              void* d_out, int out_size)
{
    const float* hidden = (const float*)d_in[0];   // [B,Q,256]
    const float* enc    = (const float*)d_in[1];   // [B,S,256]
    const float* refp   = (const float*)d_in[2];   // [B,Q,L,2]
    // d_in[3] = spatial_shapes (static, hardcoded)
    const float* off_w  = (const float*)d_in[4];   // [192,256]
    const float* off_b  = (const float*)d_in[5];
    const float* aw_w   = (const float*)d_in[6];   // [96,256]
    const float* aw_b   = (const float*)d_in[7];
    const float* val_w  = (const float*)d_in[8];   // [256,256]
    const float* val_b  = (const float*)d_in[9];
    const float* out_w  = (const float*)d_in[10];  // [256,256]
    const float* out_b  = (const float*)d_in[11];
    float* out = (float*)d_out;

    __half *p_hid_h, *p_enc_h, *p_msda_h, *p_val_h;
    __half *p_valw, *p_offw, *p_aww, *p_outw;
    float  *p_off, *p_aw;
    cudaGetSymbolAddress((void**)&p_hid_h,  g_hidden_h);
    cudaGetSymbolAddress((void**)&p_enc_h,  g_enc_h);
    cudaGetSymbolAddress((void**)&p_msda_h, g_msda_h);
    cudaGetSymbolAddress((void**)&p_val_h,  g_value_h4);
    cudaGetSymbolAddress((void**)&p_valw,   g_valw_h);
    cudaGetSymbolAddress((void**)&p_offw,   g_offw_h);
    cudaGetSymbolAddress((void**)&p_aww,    g_aww_h);
    cudaGetSymbolAddress((void**)&p_outw,   g_outw_h);
    cudaGetSymbolAddress((void**)&p_off,    g_off);
    cudaGetSymbolAddress((void**)&p_aw,     g_aw);

    const int MB = MROWS / 128;   // 336
    dim3 blk(256);

    // fp32 -> fp16 conversions
    const int nA8 = MROWS * EMBED / 8;     // 1376256
    f2h_kernel<<<(nA8 + 255) / 256, blk>>>((const float4*)hidden, (uint4*)p_hid_h, nA8);
    f2h_kernel<<<(nA8 + 255) / 256, blk>>>((const float4*)enc,    (uint4*)p_enc_h, nA8);
    f2h_kernel<<<32, blk>>>((const float4*)val_w, (uint4*)p_valw, 256 * 256 / 8);
    f2h_kernel<<<24, blk>>>((const float4*)off_w, (uint4*)p_offw, 192 * 256 / 8);
    f2h_kernel<<<12, blk>>>((const float4*)aw_w,  (uint4*)p_aww,  96 * 256 / 8);
    f2h_kernel<<<32, blk>>>((const float4*)out_w, (uint4*)p_outw, 256 * 256 / 8);

    // value projection -> fp16 [B,S,H,D]
    hgemm_wt_bias<<<dim3(4, MB), blk>>>(p_enc_h, p_valw, val_b, nullptr, (__half*)p_val_h, 256);
    // sampling offsets: N=192 (fp32 out)
    hgemm_wt_bias<<<dim3(3, MB), blk>>>(p_hid_h, p_offw, off_b, p_off, nullptr, 192);
    // attention weights: N=96 (fp32 out)
    hgemm_wt_bias<<<dim3(2, MB), blk>>>(p_hid_h, p_aww, aw_b, p_aw, nullptr, 96);

    // deformable sampling -> fp16 msda
    msda_sample_kernel<<<MROWS / QB, blk>>>(refp);

    // output projection (fp32 out to d_out)
    hgemm_wt_bias<<<dim3(4, MB), blk>>>(p_msda_h, p_outw, out_b, out, nullptr, 256);
}

// round 6
// speedup vs baseline: 1.7902x; 1.0255x over previous
#include <cuda_runtime.h>
#include <cuda_fp16.h>
#include <math.h>

// Problem constants (static in the reference)
#define EMBED   256
#define HEADS   8
#define LEVELS  3
#define POINTS  4
#define DHEAD   32
#define BATCH   2
#define SEQ     21504          // 128*128 + 64*64 + 32*32
#define NQUERY  21504
#define MROWS   (BATCH * NQUERY)   // 43008

#define SEQP    (SEQ + 2)                 // padded pixels per (b,h) plane
#define NPLANE  (BATCH * HEADS)           // 16
#define CPYB_H  ((size_t)NPLANE * SEQP * DHEAD)   // halves per copy
#define CPYB_U4 (CPYB_H / 8)                      // uint4 per copy

// Scratch (device globals; no allocation allowed)
__device__ uint4  g_valrep[2 * CPYB_U4];          // fp16 value [copy][B,H,Sp,D]
__device__ __half g_hidden_h[(size_t)MROWS * EMBED];
__device__ __half g_enc_h   [(size_t)BATCH * SEQ * EMBED];
__device__ __half g_msda_h  [(size_t)MROWS * EMBED];
__device__ __half g_valw_h  [256 * 256];
__device__ __half g_outw_h  [256 * 256];
__device__ __half g_obw_h   [288 * 256];          // off(192) + aw(96) weights
__device__ float  g_obb     [288];                // concat bias
__device__ float  g_offaw   [(size_t)MROWS * 288];// fused off+aw GEMM output

// ---------------------------------------------------------------------------
// Mega fp32->fp16 conversion: hidden, enc, val_w, out_w, off_w|aw_w concat.
// Also copies the concat bias.
// ---------------------------------------------------------------------------
#define SEG_H   1376256                 // hidden uint4
#define SEG_E   (SEG_H + 1376256)       // enc
#define SEG_VW  (SEG_E + 8192)
#define SEG_OW  (SEG_VW + 8192)
#define SEG_OFW (SEG_OW + 6144)
#define SEG_AWW (SEG_OFW + 3072)        // total 2778112

__global__ void f2h_mega(const float4* __restrict__ hidden,
                         const float4* __restrict__ enc,
                         const float4* __restrict__ valw,
                         const float4* __restrict__ outw,
                         const float4* __restrict__ offw,
                         const float4* __restrict__ aww,
                         const float*  __restrict__ offb,
                         const float*  __restrict__ awb)
{
    const int gid = blockIdx.x * blockDim.x + threadIdx.x;
    if (gid < 288)
        g_obb[gid] = (gid < 192) ? offb[gid] : awb[gid - 192];
    if (gid >= SEG_AWW) return;

    const float4* src;
    uint4* dst;
    int idx;
    if (gid < SEG_H)        { src = hidden; dst = (uint4*)g_hidden_h; idx = gid; }
    else if (gid < SEG_E)   { src = enc;    dst = (uint4*)g_enc_h;    idx = gid - SEG_H; }
    else if (gid < SEG_VW)  { src = valw;   dst = (uint4*)g_valw_h;   idx = gid - SEG_E; }
    else if (gid < SEG_OW)  { src = outw;   dst = (uint4*)g_outw_h;   idx = gid - SEG_VW; }
    else if (gid < SEG_OFW) { src = offw;   dst = (uint4*)g_obw_h;    idx = gid - SEG_OW; }
    else                    { src = aww;    dst = (uint4*)g_obw_h + 6144; idx = gid - SEG_OFW; }

    float4 f0 = src[2 * idx];
    float4 f1 = src[2 * idx + 1];
    __half2 h0 = __floats2half2_rn(f0.x, f0.y);
    __half2 h1 = __floats2half2_rn(f0.z, f0.w);
    __half2 h2 = __floats2half2_rn(f1.x, f1.y);
    __half2 h3 = __floats2half2_rn(f1.z, f1.w);
    uint4 o;
    o.x = *reinterpret_cast<unsigned*>(&h0);
    o.y = *reinterpret_cast<unsigned*>(&h1);
    o.z = *reinterpret_cast<unsigned*>(&h2);
    o.w = *reinterpret_cast<unsigned*>(&h3);
    dst[idx] = o;
}

__device__ __forceinline__ void cp_async16(unsigned smem_addr, const void* gptr, int src_size) {
    asm volatile("cp.async.cg.shared.global [%0], [%1], 16, %2;\n"
                 :: "r"(smem_addr), "l"(gptr), "r"(src_size));
}
__device__ __forceinline__ void ldmatrix_x4(unsigned* r, unsigned addr) {
    asm volatile("ldmatrix.sync.aligned.m8n8.x4.shared.b16 {%0,%1,%2,%3}, [%4];"
                 : "=r"(r[0]), "=r"(r[1]), "=r"(r[2]), "=r"(r[3]) : "r"(addr));
}

// ---------------------------------------------------------------------------
// FP16 tensor-core GEMM: C[M,N] = A[M,256] * W[N,256]^T + bias[N]
// BM=128, BN=64, BK=64; 256 threads = 8 warps (4m x 2n), warp tile 32x32.
// to_value=0: float C.  to_value=1: write fp16 to g_valrep in replicated
// [B,H,Sp,D] layout (two copies, copy B shifted +1 pixel).
// ---------------------------------------------------------------------------
__global__ void __launch_bounds__(256) hgemm_wt_bias(
    const __half* __restrict__ A, const __half* __restrict__ W,
    const float* __restrict__ bias, float* __restrict__ C,
    int N, int to_value)
{
    const int K = 256;
    __shared__ __align__(16) char smem[2 * (16384 + 8192)];
    const unsigned smem_u = (unsigned)__cvta_generic_to_shared(smem);

    const int tid  = threadIdx.x;
    const int wid  = tid >> 5;
    const int lane = tid & 31;

    const int m0 = blockIdx.y * 128;
    const int n0 = blockIdx.x * 64;
    const int warp_m = (wid & 3) * 32;
    const int warp_n = (wid >> 2) * 32;

    const int s_row0 = tid >> 3;
    const int s_c    = tid & 7;

    float acc[2][4][4];
#pragma unroll
    for (int mi = 0; mi < 2; mi++)
#pragma unroll
        for (int ni = 0; ni < 4; ni++)
#pragma unroll
            for (int c = 0; c < 4; c++) acc[mi][ni][c] = 0.f;

    auto load_stage = [&](int stage, int k0) {
        const unsigned a_base = smem_u + stage * 24576;
        const unsigned w_base = a_base + 16384;
#pragma unroll
        for (int i = 0; i < 4; i++) {
            int row = s_row0 + i * 32;
            int sw  = s_c ^ (row & 7);
            cp_async16(a_base + (row * 8 + sw) * 16,
                       &A[(size_t)(m0 + row) * K + k0 + s_c * 8], 16);
        }
#pragma unroll
        for (int i = 0; i < 2; i++) {
            int row = s_row0 + i * 32;
            int sw  = s_c ^ (row & 7);
            int n   = n0 + row;
            int ok  = (n < N) ? 16 : 0;
            const __half* src = (n < N) ? &W[(size_t)n * K + k0 + s_c * 8] : W;
            cp_async16(w_base + (row * 8 + sw) * 16, src, ok);
        }
        asm volatile("cp.async.commit_group;\n");
    };

    load_stage(0, 0);

    const int a_moff = (lane & 8) + (lane & 7);
    const int a_koff = (lane & 16) >> 1;
    const int b_noff = ((lane & 16) >> 1) + (lane & 7);
    const int b_koff = lane & 8;

    const int NIT = K / 64;   // 4
#pragma unroll 1
    for (int it = 0; it < NIT; it++) {
        const int cur = it & 1;
        if (it + 1 < NIT) {
            load_stage(cur ^ 1, (it + 1) * 64);
            asm volatile("cp.async.wait_group 1;\n");
        } else {
            asm volatile("cp.async.wait_group 0;\n");
        }
        __syncthreads();

        const unsigned a_base = smem_u + cur * 24576;
        const unsigned w_base = a_base + 16384;

#pragma unroll
        for (int kk = 0; kk < 4; kk++) {
            unsigned a[2][4], b[2][4];
#pragma unroll
            for (int mi = 0; mi < 2; mi++) {
                int m_r = warp_m + mi * 16 + a_moff;
                int k_h = kk * 16 + a_koff;
                int sw  = (k_h >> 3) ^ (m_r & 7);
                ldmatrix_x4(a[mi], a_base + (m_r * 8 + sw) * 16);
            }
#pragma unroll
            for (int bi = 0; bi < 2; bi++) {
                int n_r = warp_n + bi * 16 + b_noff;
                int k_h = kk * 16 + b_koff;
                int sw  = (k_h >> 3) ^ (n_r & 7);
                ldmatrix_x4(b[bi], w_base + (n_r * 8 + sw) * 16);
            }
#pragma unroll
            for (int mi = 0; mi < 2; mi++)
#pragma unroll
                for (int ni = 0; ni < 4; ni++) {
                    unsigned b0 = b[ni >> 1][(ni & 1) * 2];
                    unsigned b1 = b[ni >> 1][(ni & 1) * 2 + 1];
                    asm volatile(
                        "mma.sync.aligned.m16n8k16.row.col.f32.f16.f16.f32 "
                        "{%0,%1,%2,%3}, {%4,%5,%6,%7}, {%8,%9}, {%0,%1,%2,%3};"
                        : "+f"(acc[mi][ni][0]), "+f"(acc[mi][ni][1]),
                          "+f"(acc[mi][ni][2]), "+f"(acc[mi][ni][3])
                        : "r"(a[mi][0]), "r"(a[mi][1]), "r"(a[mi][2]), "r"(a[mi][3]),
                          "r"(b0), "r"(b1));
                }
        }
        __syncthreads();
    }

    // epilogue
    const int g = lane >> 2;
    const int t = lane & 3;
    __half* Vh = reinterpret_cast<__half*>(g_valrep);
#pragma unroll
    for (int mi = 0; mi < 2; mi++) {
        int row0 = m0 + warp_m + mi * 16 + g;
#pragma unroll
        for (int ni = 0; ni < 4; ni++) {
            int col = n0 + warp_n + ni * 8 + t * 2;
            if (col < N) {
                float bx = bias[col], by = bias[col + 1];
                float v00 = acc[mi][ni][0] + bx, v01 = acc[mi][ni][1] + by;
                float v10 = acc[mi][ni][2] + bx, v11 = acc[mi][ni][3] + by;
                if (to_value) {
                    int b  = row0 >= SEQ;
                    int s  = row0 - b * SEQ;
                    int h  = col >> 5;
                    int d  = col & 31;
                    size_t plane = (size_t)(b * 8 + h) * SEQP;
                    __half2 p0 = __floats2half2_rn(v00, v01);
                    __half2 p1 = __floats2half2_rn(v10, v11);
                    // copy A
                    *reinterpret_cast<__half2*>(&Vh[(plane + s    ) * 32 + d]) = p0;
                    *reinterpret_cast<__half2*>(&Vh[(plane + s + 8) * 32 + d]) = p1;
                    // copy B (+1 pixel shift)
                    *reinterpret_cast<__half2*>(&Vh[CPYB_H + (plane + s + 1) * 32 + d]) = p0;
                    *reinterpret_cast<__half2*>(&Vh[CPYB_H + (plane + s + 9) * 32 + d]) = p1;
                } else {
                    *reinterpret_cast<float2*>(&C[(size_t)row0 * N + col]) =
                        make_float2(v00, v01);
                    *reinterpret_cast<float2*>(&C[(size_t)(row0 + 8) * N + col]) =
                        make_float2(v10, v11);
                }
            }
        }
    }
}

// ---------------------------------------------------------------------------
// Deformable sampling. Value fp16 [copy][B,H,Sp,D]; a sample's two x-pixels
// are one ALIGNED 128B load (copy chosen by xb parity). Unit = 8 lanes:
// lanes 0-3 accumulate pixel xb, 4-7 pixel xb+1; shfl_xor(4)-add at end.
// Block = 8 queries x 8 heads = 64 units, 2 passes of 32 units.
// ---------------------------------------------------------------------------
#define QB 8
#define NSAMP (QB * HEADS * LEVELS * POINTS)   // 768

__global__ void __launch_bounds__(256) msda_sample_kernel(
    const float* __restrict__ refp)
{
    __shared__ float  s_aw[QB * HEADS * 12];
    __shared__ int2   s_off[NSAMP];            // row0/row1 offsets (uint4 units)
    __shared__ float4 s_wt[NSAMP];             // (w0l, w0r, w1l, w1r)

    const int tid = threadIdx.x;
    const int bq0 = blockIdx.x * QB;

    // Phase 1a: softmax once per (q, h); logits at g_offaw[.. , 192+]
    if (tid < QB * HEADS) {
        const int bqi = tid >> 3;
        const int h   = tid & 7;
        const float* awp = g_offaw + (size_t)(bq0 + bqi) * 288 + 192 + h * 12;
        float w[12];
        float mx = -1e30f;
#pragma unroll
        for (int j = 0; j < 12; j++) { w[j] = awp[j]; mx = fmaxf(mx, w[j]); }
        float s = 0.f;
#pragma unroll
        for (int j = 0; j < 12; j++) { w[j] = __expf(w[j] - mx); s += w[j]; }
        const float invs = 1.f / s;
#pragma unroll
        for (int j = 0; j < 12; j++) s_aw[tid * 12 + j] = w[j] * invs;
    }
    __syncthreads();

    // Phase 1b: per-sample params (3 samples per thread)
    const int lvlW[3]     = {128, 64, 32};
    const int lvlStart[3] = {0, 16384, 20480};
#pragma unroll
    for (int i = 0; i < 3; i++) {
        const int sid = tid + i * 256;
        const int bqi = sid / 96;
        const int r   = sid - bqi * 96;
        const int h   = r / 12;
        const int lp  = r - h * 12;
        const int l   = lp >> 2;

        const int bq = bq0 + bqi;
        const int b  = (bq >= NQUERY) ? 1 : 0;
        const int Wl = lvlW[l];
        const float fW = (float)Wl;

        const float ox = g_offaw[(size_t)bq * 288 + h * 24 + lp * 2 + 0];
        const float oy = g_offaw[(size_t)bq * 288 + h * 24 + lp * 2 + 1];
        const float rx = refp[(size_t)bq * 6 + l * 2 + 0];
        const float ry = refp[(size_t)bq * 6 + l * 2 + 1];

        const float x = fmaf(rx, fW, ox) - 0.5f;
        const float y = fmaf(ry, fW, oy) - 0.5f;
        const float xf = floorf(x), yf = floorf(y);
        const float wx = x - xf,    wy = y - yf;
        const int x0 = (int)xf, y0 = (int)yf;

        // x pair weights: pair = (xb, xb+1), xb = clamp(x0)
        const int xb = min(max(x0, 0), Wl - 1);
        float wxl = (x0 >= 0 && x0 < Wl) ? (1.f - wx) : ((x0 == -1) ? wx : 0.f);
        float wxr = (x0 >= 0 && x0 + 1 < Wl) ? wx : 0.f;
        // y rows
        const int y0c = min(max(y0, 0), Wl - 1);
        const int y1c = min(max(y0 + 1, 0), Wl - 1);
        float wy0 = (y0 >= 0 && y0 < Wl) ? (1.f - wy) : 0.f;
        float wy1 = (y0 + 1 >= 0 && y0 + 1 < Wl) ? wy : 0.f;

        const float ws = s_aw[(bqi * 8 + h) * 12 + lp];
        float4 wt;
        wt.x = ws * wy0 * wxl;
        wt.y = ws * wy0 * wxr;
        wt.z = ws * wy1 * wxl;
        wt.w = ws * wy1 * wxr;

        // offsets in uint4 units into g_valrep; parity of xb picks the copy
        const int plane = (b * 8 + h) * SEQP;
        const int idx0  = lvlStart[l] + y0c * Wl + xb;
        const int idx1  = lvlStart[l] + y1c * Wl + xb;
        const int odd   = xb & 1;
        const int cbase = odd ? ((int)CPYB_U4 + 4) : 0;   // +1 pixel in copy B
        int2 off;
        off.x = cbase + (plane + idx0) * 4;
        off.y = cbase + (plane + idx1) * 4;

        s_off[sid] = off;
        s_wt[sid]  = wt;
    }
    __syncthreads();

    // Phase 2: gather. 2 passes x 32 units x 8 lanes.
    const uint4* __restrict__ VR = g_valrep;
    const int ll = tid & 7;          // lane in unit
#pragma unroll
    for (int pass = 0; pass < 2; pass++) {
        const int u   = (tid >> 3) + pass * 32;   // 0..63
        const int bqi = u >> 3;
        const int h   = u & 7;

        float acc[8];
#pragma unroll
        for (int c = 0; c < 8; c++) acc[c] = 0.f;

#pragma unroll
        for (int s12 = 0; s12 < 12; s12++) {
            const int sid = u * 12 + s12;
            const int2   off = s_off[sid];
            const float4 wt  = s_wt[sid];
            uint4 r0 = VR[off.x + ll];
            uint4 r1 = VR[off.y + ll];
            const float wa = (ll & 4) ? wt.y : wt.x;   // row0 weight (this side)
            const float wb = (ll & 4) ? wt.w : wt.z;   // row1 weight
            const __half2* p0 = reinterpret_cast<const __half2*>(&r0);
            const __half2* p1 = reinterpret_cast<const __half2*>(&r1);
#pragma unroll
            for (int j = 0; j < 4; j++) {
                float2 f0 = __half22float2(p0[j]);
                float2 f1 = __half22float2(p1[j]);
                acc[2*j]   = fmaf(wa, f0.x, fmaf(wb, f1.x, acc[2*j]));
                acc[2*j+1] = fmaf(wa, f0.y, fmaf(wb, f1.y, acc[2*j+1]));
            }
        }
        // combine pixel sides: lanes c and c+4 hold the two halves
#pragma unroll
        for (int c = 0; c < 8; c++)
            acc[c] += __shfl_xor_sync(0xffffffffu, acc[c], 4);

        if (ll < 4) {
            __half2 o0 = __floats2half2_rn(acc[0], acc[1]);
            __half2 o1 = __floats2half2_rn(acc[2], acc[3]);
            __half2 o2 = __floats2half2_rn(acc[4], acc[5]);
            __half2 o3 = __floats2half2_rn(acc[6], acc[7]);
            uint4 ov;
            ov.x = *reinterpret_cast<unsigned*>(&o0);
            ov.y = *reinterpret_cast<unsigned*>(&o1);
            ov.z = *reinterpret_cast<unsigned*>(&o2);
            ov.w = *reinterpret_cast<unsigned*>(&o3);
            uint4* outp = reinterpret_cast<uint4*>(g_msda_h)
                        + (size_t)(bq0 + bqi) * 32 + h * 4 + ll;
            *outp = ov;
        }
    }
}

// ---------------------------------------------------------------------------

extern "C" void kernel_launch(void* const* d_in, const int* in_sizes, int n_in,
                              void* d_out, int out_size)
{
    const float* hidden = (const float*)d_in[0];   // [B,Q,256]
    const float* enc    = (const float*)d_in[1];   // [B,S,256]
    const float* refp   = (const float*)d_in[2];   // [B,Q,L,2]
    // d_in[3] = spatial_shapes (static, hardcoded)
    const float* off_w  = (const float*)d_in[4];   // [192,256]
    const float* off_b  = (const float*)d_in[5];
    const float* aw_w   = (const float*)d_in[6];   // [96,256]
    const float* aw_b   = (const float*)d_in[7];
    const float* val_w  = (const float*)d_in[8];   // [256,256]
    const float* val_b  = (const float*)d_in[9];
    const float* out_w  = (const float*)d_in[10];  // [256,256]
    const float* out_b  = (const float*)d_in[11];
    float* out = (float*)d_out;

    __half *p_hid_h, *p_enc_h, *p_msda_h, *p_valw, *p_outw, *p_obw;
    float  *p_obb, *p_offaw;
    cudaGetSymbolAddress((void**)&p_hid_h,  g_hidden_h);
    cudaGetSymbolAddress((void**)&p_enc_h,  g_enc_h);
    cudaGetSymbolAddress((void**)&p_msda_h, g_msda_h);
    cudaGetSymbolAddress((void**)&p_valw,   g_valw_h);
    cudaGetSymbolAddress((void**)&p_outw,   g_outw_h);
    cudaGetSymbolAddress((void**)&p_obw,    g_obw_h);
    cudaGetSymbolAddress((void**)&p_obb,    g_obb);
    cudaGetSymbolAddress((void**)&p_offaw,  g_offaw);

    const int MB = MROWS / 128;   // 336
    dim3 blk(256);

    // all fp32 -> fp16 conversions + bias concat in one launch
    f2h_mega<<<(SEG_AWW + 255) / 256, blk>>>(
        (const float4*)hidden, (const float4*)enc,
        (const float4*)val_w, (const float4*)out_w,
        (const float4*)off_w, (const float4*)aw_w,
        off_b, aw_b);

    // value projection -> replicated fp16 [B,H,Sp,D] (two copies)
    hgemm_wt_bias<<<dim3(4, MB), blk>>>(p_enc_h, p_valw, val_b, nullptr, 256, 1);
    // fused sampling offsets + attention weights: N=288 (fp32 out)
    hgemm_wt_bias<<<dim3(5, MB), blk>>>(p_hid_h, p_obw, p_obb, p_offaw, 288, 0);

    // deformable sampling -> fp16 msda
    msda_sample_kernel<<<MROWS / QB, blk>>>(refp);

    // output projection (fp32 out to d_out)
    hgemm_wt_bias<<<dim3(4, MB), blk>>>(p_msda_h, p_outw, out_b, out, 256, 0);
}

// round 7
// speedup vs baseline: 1.9735x; 1.1024x over previous
#include <cuda_runtime.h>
#include <cuda_fp16.h>
#include <math.h>

// Problem constants (static in the reference)
#define EMBED   256
#define HEADS   8
#define LEVELS  3
#define POINTS  4
#define DHEAD   32
#define BATCH   2
#define SEQ     21504          // 128*128 + 64*64 + 32*32
#define NQUERY  21504
#define MROWS   (BATCH * NQUERY)   // 43008

#define SEQP    (SEQ + 2)                 // padded pixels per (b,h) plane
#define NPLANE  (BATCH * HEADS)           // 16
#define CPYB_H  ((size_t)NPLANE * SEQP * DHEAD)   // halves per copy
#define CPYB_U4 (CPYB_H / 8)                      // uint4 per copy

// Scratch (device globals; no allocation allowed)
__device__ uint4  g_valrep[2 * CPYB_U4];          // fp16 value [copy][B,H,Sp,D]
__device__ __half g_hidden_h[(size_t)MROWS * EMBED];
__device__ __half g_enc_h   [(size_t)BATCH * SEQ * EMBED];
__device__ __half g_msda_h  [(size_t)MROWS * EMBED];
__device__ __half g_valw_h  [256 * 256];
__device__ __half g_outw_h  [256 * 256];
__device__ __half g_obw_h   [288 * 256];          // off(192) + aw(96) weights
__device__ float  g_obb     [288];                // concat bias
__device__ __half g_offaw_h [(size_t)MROWS * 288];// fused off+aw output (fp16)

// ---------------------------------------------------------------------------
// Mega fp32->fp16 conversion: hidden, enc, val_w, out_w, off_w|aw_w concat.
// ---------------------------------------------------------------------------
#define SEG_H   1376256                 // hidden uint4
#define SEG_E   (SEG_H + 1376256)       // enc
#define SEG_VW  (SEG_E + 8192)
#define SEG_OW  (SEG_VW + 8192)
#define SEG_OFW (SEG_OW + 6144)
#define SEG_AWW (SEG_OFW + 3072)        // total 2778112

__global__ void f2h_mega(const float4* __restrict__ hidden,
                         const float4* __restrict__ enc,
                         const float4* __restrict__ valw,
                         const float4* __restrict__ outw,
                         const float4* __restrict__ offw,
                         const float4* __restrict__ aww,
                         const float*  __restrict__ offb,
                         const float*  __restrict__ awb)
{
    const int gid = blockIdx.x * blockDim.x + threadIdx.x;
    if (gid < 288)
        g_obb[gid] = (gid < 192) ? offb[gid] : awb[gid - 192];
    if (gid >= SEG_AWW) return;

    const float4* src;
    uint4* dst;
    int idx;
    if (gid < SEG_H)        { src = hidden; dst = (uint4*)g_hidden_h; idx = gid; }
    else if (gid < SEG_E)   { src = enc;    dst = (uint4*)g_enc_h;    idx = gid - SEG_H; }
    else if (gid < SEG_VW)  { src = valw;   dst = (uint4*)g_valw_h;   idx = gid - SEG_E; }
    else if (gid < SEG_OW)  { src = outw;   dst = (uint4*)g_outw_h;   idx = gid - SEG_VW; }
    else if (gid < SEG_OFW) { src = offw;   dst = (uint4*)g_obw_h;    idx = gid - SEG_OW; }
    else                    { src = aww;    dst = (uint4*)g_obw_h + 6144; idx = gid - SEG_OFW; }

    float4 f0 = src[2 * idx];
    float4 f1 = src[2 * idx + 1];
    __half2 h0 = __floats2half2_rn(f0.x, f0.y);
    __half2 h1 = __floats2half2_rn(f0.z, f0.w);
    __half2 h2 = __floats2half2_rn(f1.x, f1.y);
    __half2 h3 = __floats2half2_rn(f1.z, f1.w);
    uint4 o;
    o.x = *reinterpret_cast<unsigned*>(&h0);
    o.y = *reinterpret_cast<unsigned*>(&h1);
    o.z = *reinterpret_cast<unsigned*>(&h2);
    o.w = *reinterpret_cast<unsigned*>(&h3);
    dst[idx] = o;
}

__device__ __forceinline__ void cp_async16(unsigned smem_addr, const void* gptr, int src_size) {
    asm volatile("cp.async.cg.shared.global [%0], [%1], 16, %2;\n"
                 :: "r"(smem_addr), "l"(gptr), "r"(src_size));
}
__device__ __forceinline__ void ldmatrix_x4(unsigned* r, unsigned addr) {
    asm volatile("ldmatrix.sync.aligned.m8n8.x4.shared.b16 {%0,%1,%2,%3}, [%4];"
                 : "=r"(r[0]), "=r"(r[1]), "=r"(r[2]), "=r"(r[3]) : "r"(addr));
}

// ---------------------------------------------------------------------------
// FP16 GEMM core: C[M,N] = A[M,256] * W[N,256]^T + bias[N]
// BM=128, BN=64, BK=32, 4-stage cp.async pipeline (12KB/stage, 48KB total).
// Smem layout: two logical 64B rows packed per 128B physical row, chunk slot
// = (c | ((r&1)<<2)) ^ ((r>>1)&7)  -- conflict-free for cp.async & ldmatrix.
// MODE: 0 = fp32 C, 1 = value replicated fp16 (g_valrep), 2 = fp16 row-288
// (g_offaw_h).
// ---------------------------------------------------------------------------
template<int MODE>
__device__ __forceinline__ void hgemm_core(
    const __half* __restrict__ A, const __half* __restrict__ W,
    const float* __restrict__ bias, float* __restrict__ C,
    int N, int n0, char* smem)
{
    const int K = 256;
    const unsigned smem_u = (unsigned)__cvta_generic_to_shared(smem);

    const int tid  = threadIdx.x;
    const int wid  = tid >> 5;
    const int lane = tid & 31;

    const int m0 = blockIdx.y * 128;
    const int warp_m = (wid & 3) * 32;
    const int warp_n = (wid >> 2) * 32;

    float acc[2][4][4];
#pragma unroll
    for (int mi = 0; mi < 2; mi++)
#pragma unroll
        for (int ni = 0; ni < 4; ni++)
#pragma unroll
            for (int c = 0; c < 4; c++) acc[mi][ni][c] = 0.f;

    auto load_stage = [&](int stage, int k0) {
        const unsigned a_base = smem_u + stage * 12288;
        const unsigned w_base = a_base + 8192;
        // A: 128 rows x 4 chunks = 512, 2 per thread
#pragma unroll
        for (int i = 0; i < 2; i++) {
            int idx = tid + i * 256;
            int r = idx >> 2, c = idx & 3;
            int pr = r >> 1;
            int slot = (c | ((r & 1) << 2)) ^ (pr & 7);
            cp_async16(a_base + pr * 128 + slot * 16,
                       &A[(size_t)(m0 + r) * K + k0 + c * 8], 16);
        }
        // W: 64 rows x 4 chunks = 256, 1 per thread
        {
            int r = tid >> 2, c = tid & 3;
            int pr = r >> 1;
            int slot = (c | ((r & 1) << 2)) ^ (pr & 7);
            int n  = n0 + r;
            int ok = (n < N) ? 16 : 0;
            const __half* src = (n < N) ? &W[(size_t)n * K + k0 + c * 8] : W;
            cp_async16(w_base + pr * 128 + slot * 16, src, ok);
        }
        asm volatile("cp.async.commit_group;\n");
    };

    load_stage(0, 0);
    load_stage(1, 32);
    load_stage(2, 64);

    const int a_lr_off = (lane & 8) + (lane & 7);   // 0..15
    const int a_cx     = (lane >> 4) & 1;           // chunk +0/+1
    const int b_lr_off = ((lane & 16) >> 1) + (lane & 7);
    const int b_cx     = (lane >> 3) & 1;

    const int NIT = 8;
#pragma unroll
    for (int it = 0; it < NIT; it++) {
        if (it <= NIT - 3)      asm volatile("cp.async.wait_group 2;\n");
        else if (it == NIT - 2) asm volatile("cp.async.wait_group 1;\n");
        else                    asm volatile("cp.async.wait_group 0;\n");
        __syncthreads();
        if (it + 3 < NIT) load_stage((it + 3) & 3, (it + 3) * 32);

        const unsigned a_base = smem_u + (it & 3) * 12288;
        const unsigned w_base = a_base + 8192;

#pragma unroll
        for (int kk = 0; kk < 2; kk++) {
            unsigned a[2][4], b[2][4];
#pragma unroll
            for (int mi = 0; mi < 2; mi++) {
                int lr = warp_m + mi * 16 + a_lr_off;
                int c  = kk * 2 + a_cx;
                int pr = lr >> 1;
                int slot = (c | ((lr & 1) << 2)) ^ (pr & 7);
                ldmatrix_x4(a[mi], a_base + pr * 128 + slot * 16);
            }
#pragma unroll
            for (int bi = 0; bi < 2; bi++) {
                int lr = warp_n + bi * 16 + b_lr_off;
                int c  = kk * 2 + b_cx;
                int pr = lr >> 1;
                int slot = (c | ((lr & 1) << 2)) ^ (pr & 7);
                ldmatrix_x4(b[bi], w_base + pr * 128 + slot * 16);
            }
#pragma unroll
            for (int mi = 0; mi < 2; mi++)
#pragma unroll
                for (int ni = 0; ni < 4; ni++) {
                    unsigned b0 = b[ni >> 1][(ni & 1) * 2];
                    unsigned b1 = b[ni >> 1][(ni & 1) * 2 + 1];
                    asm volatile(
                        "mma.sync.aligned.m16n8k16.row.col.f32.f16.f16.f32 "
                        "{%0,%1,%2,%3}, {%4,%5,%6,%7}, {%8,%9}, {%0,%1,%2,%3};"
                        : "+f"(acc[mi][ni][0]), "+f"(acc[mi][ni][1]),
                          "+f"(acc[mi][ni][2]), "+f"(acc[mi][ni][3])
                        : "r"(a[mi][0]), "r"(a[mi][1]), "r"(a[mi][2]), "r"(a[mi][3]),
                          "r"(b0), "r"(b1));
                }
        }
    }

    // epilogue
    const int g = lane >> 2;
    const int t = lane & 3;
    __half* Vh = reinterpret_cast<__half*>(g_valrep);
#pragma unroll
    for (int mi = 0; mi < 2; mi++) {
        int row0 = m0 + warp_m + mi * 16 + g;
#pragma unroll
        for (int ni = 0; ni < 4; ni++) {
            int col = n0 + warp_n + ni * 8 + t * 2;
            if (col < N) {
                float bx = bias[col], by = bias[col + 1];
                float v00 = acc[mi][ni][0] + bx, v01 = acc[mi][ni][1] + by;
                float v10 = acc[mi][ni][2] + bx, v11 = acc[mi][ni][3] + by;
                if (MODE == 1) {
                    int b  = row0 >= SEQ;
                    int s  = row0 - b * SEQ;
                    int h  = col >> 5;
                    int d  = col & 31;
                    size_t plane = (size_t)(b * 8 + h) * SEQP;
                    __half2 p0 = __floats2half2_rn(v00, v01);
                    __half2 p1 = __floats2half2_rn(v10, v11);
                    *reinterpret_cast<__half2*>(&Vh[(plane + s    ) * 32 + d]) = p0;
                    *reinterpret_cast<__half2*>(&Vh[(plane + s + 8) * 32 + d]) = p1;
                    *reinterpret_cast<__half2*>(&Vh[CPYB_H + (plane + s + 1) * 32 + d]) = p0;
                    *reinterpret_cast<__half2*>(&Vh[CPYB_H + (plane + s + 9) * 32 + d]) = p1;
                } else if (MODE == 2) {
                    *reinterpret_cast<__half2*>(&g_offaw_h[(size_t)row0 * 288 + col]) =
                        __floats2half2_rn(v00, v01);
                    *reinterpret_cast<__half2*>(&g_offaw_h[(size_t)(row0 + 8) * 288 + col]) =
                        __floats2half2_rn(v10, v11);
                } else {
                    *reinterpret_cast<float2*>(&C[(size_t)row0 * N + col]) =
                        make_float2(v00, v01);
                    *reinterpret_cast<float2*>(&C[(size_t)(row0 + 8) * N + col]) =
                        make_float2(v10, v11);
                }
            }
        }
    }
}

// Merged value-proj (x<4) + offsets/aw-proj (x>=4) launch
__global__ void __launch_bounds__(256) fused_proj_gemm(
    const __half* __restrict__ enc_h, const __half* __restrict__ valw,
    const float* __restrict__ valb,
    const __half* __restrict__ hid_h, const __half* __restrict__ obw,
    const float* __restrict__ obb)
{
    __shared__ __align__(16) char smem[49152];
    if (blockIdx.x < 4)
        hgemm_core<1>(enc_h, valw, valb, nullptr, 256, blockIdx.x * 64, smem);
    else
        hgemm_core<2>(hid_h, obw, obb, nullptr, 288, (blockIdx.x - 4) * 64, smem);
}

__global__ void __launch_bounds__(256) out_proj_gemm(
    const __half* __restrict__ msda, const __half* __restrict__ outw,
    const float* __restrict__ outb, float* __restrict__ out)
{
    __shared__ __align__(16) char smem[49152];
    hgemm_core<0>(msda, outw, outb, out, 256, blockIdx.x * 64, smem);
}

// ---------------------------------------------------------------------------
// Deformable sampling. Value fp16 [copy][B,H,Sp,D]; x-pixel pair = one
// aligned 128B load (copy picked by xb parity). Unit = 8 lanes: lanes 0-3
// accumulate pixel xb, 4-7 pixel xb+1; shfl_xor(4)-add at end.
// Row-combine in half2 (products round once in fp16; accumulate fp32).
// ---------------------------------------------------------------------------
#define QB 8
#define NSAMP (QB * HEADS * LEVELS * POINTS)   // 768

__global__ void __launch_bounds__(256) msda_sample_kernel(
    const float* __restrict__ refp)
{
    __shared__ float  s_aw[QB * HEADS * 12];
    __shared__ int2   s_off[NSAMP];            // row0/row1 offsets (uint4 units)
    __shared__ float4 s_wt[NSAMP];             // (w0l, w0r, w1l, w1r)

    const int tid = threadIdx.x;
    const int bq0 = blockIdx.x * QB;

    // Phase 1a: softmax once per (q, h); fp16 logits at g_offaw_h[.., 192+]
    if (tid < QB * HEADS) {
        const int bqi = tid >> 3;
        const int h   = tid & 7;
        const __half* awp = g_offaw_h + (size_t)(bq0 + bqi) * 288 + 192 + h * 12;
        float w[12];
        float mx = -1e30f;
#pragma unroll
        for (int j = 0; j < 12; j++) { w[j] = __half2float(awp[j]); mx = fmaxf(mx, w[j]); }
        float s = 0.f;
#pragma unroll
        for (int j = 0; j < 12; j++) { w[j] = __expf(w[j] - mx); s += w[j]; }
        const float invs = 1.f / s;
#pragma unroll
        for (int j = 0; j < 12; j++) s_aw[tid * 12 + j] = w[j] * invs;
    }
    __syncthreads();

    // Phase 1b: per-sample params (3 samples per thread)
    const int lvlW[3]     = {128, 64, 32};
    const int lvlStart[3] = {0, 16384, 20480};
#pragma unroll
    for (int i = 0; i < 3; i++) {
        const int sid = tid + i * 256;
        const int bqi = sid / 96;
        const int r   = sid - bqi * 96;
        const int h   = r / 12;
        const int lp  = r - h * 12;
        const int l   = lp >> 2;

        const int bq = bq0 + bqi;
        const int b  = (bq >= NQUERY) ? 1 : 0;
        const int Wl = lvlW[l];
        const float fW = (float)Wl;

        const __half2 oxy = *reinterpret_cast<const __half2*>(
            g_offaw_h + (size_t)bq * 288 + h * 24 + lp * 2);
        const float ox = __low2float(oxy);
        const float oy = __high2float(oxy);
        const float rx = refp[(size_t)bq * 6 + l * 2 + 0];
        const float ry = refp[(size_t)bq * 6 + l * 2 + 1];

        const float x = fmaf(rx, fW, ox) - 0.5f;
        const float y = fmaf(ry, fW, oy) - 0.5f;
        const float xf = floorf(x), yf = floorf(y);
        const float wx = x - xf,    wy = y - yf;
        const int x0 = (int)xf, y0 = (int)yf;

        const int xb = min(max(x0, 0), Wl - 1);
        float wxl = (x0 >= 0 && x0 < Wl) ? (1.f - wx) : ((x0 == -1) ? wx : 0.f);
        float wxr = (x0 >= 0 && x0 + 1 < Wl) ? wx : 0.f;
        const int y0c = min(max(y0, 0), Wl - 1);
        const int y1c = min(max(y0 + 1, 0), Wl - 1);
        float wy0 = (y0 >= 0 && y0 < Wl) ? (1.f - wy) : 0.f;
        float wy1 = (y0 + 1 >= 0 && y0 + 1 < Wl) ? wy : 0.f;

        const float ws = s_aw[(bqi * 8 + h) * 12 + lp];
        float4 wt;
        wt.x = ws * wy0 * wxl;
        wt.y = ws * wy0 * wxr;
        wt.z = ws * wy1 * wxl;
        wt.w = ws * wy1 * wxr;

        const int plane = (b * 8 + h) * SEQP;
        const int idx0  = lvlStart[l] + y0c * Wl + xb;
        const int idx1  = lvlStart[l] + y1c * Wl + xb;
        const int odd   = xb & 1;
        const int cbase = odd ? ((int)CPYB_U4 + 4) : 0;   // +1 pixel in copy B
        int2 off;
        off.x = cbase + (plane + idx0) * 4;
        off.y = cbase + (plane + idx1) * 4;

        s_off[sid] = off;
        s_wt[sid]  = wt;
    }
    __syncthreads();

    // Phase 2: gather. 2 passes x 32 units x 8 lanes.
    const uint4* __restrict__ VR = g_valrep;
    const int ll = tid & 7;
#pragma unroll
    for (int pass = 0; pass < 2; pass++) {
        const int u   = (tid >> 3) + pass * 32;   // 0..63
        const int bqi = u >> 3;
        const int h   = u & 7;

        float acc[8];
#pragma unroll
        for (int c = 0; c < 8; c++) acc[c] = 0.f;

#pragma unroll
        for (int s12 = 0; s12 < 12; s12++) {
            const int sid = u * 12 + s12;
            const int2   off = s_off[sid];
            const float4 wt  = s_wt[sid];
            uint4 r0 = VR[off.x + ll];
            uint4 r1 = VR[off.y + ll];
            const __half2 wa2 = __float2half2_rn((ll & 4) ? wt.y : wt.x);
            const __half2 wb2 = __float2half2_rn((ll & 4) ? wt.w : wt.z);
            const __half2* p0 = reinterpret_cast<const __half2*>(&r0);
            const __half2* p1 = reinterpret_cast<const __half2*>(&r1);
#pragma unroll
            for (int j = 0; j < 4; j++) {
                __half2 tt = __hfma2(p0[j], wa2, __hmul2(p1[j], wb2));
                float2 ft = __half22float2(tt);
                acc[2*j]   += ft.x;
                acc[2*j+1] += ft.y;
            }
        }
#pragma unroll
        for (int c = 0; c < 8; c++)
            acc[c] += __shfl_xor_sync(0xffffffffu, acc[c], 4);

        if (ll < 4) {
            __half2 o0 = __floats2half2_rn(acc[0], acc[1]);
            __half2 o1 = __floats2half2_rn(acc[2], acc[3]);
            __half2 o2 = __floats2half2_rn(acc[4], acc[5]);
            __half2 o3 = __floats2half2_rn(acc[6], acc[7]);
            uint4 ov;
            ov.x = *reinterpret_cast<unsigned*>(&o0);
            ov.y = *reinterpret_cast<unsigned*>(&o1);
            ov.z = *reinterpret_cast<unsigned*>(&o2);
            ov.w = *reinterpret_cast<unsigned*>(&o3);
            uint4* outp = reinterpret_cast<uint4*>(g_msda_h)
                        + (size_t)(bq0 + bqi) * 32 + h * 4 + ll;
            *outp = ov;
        }
    }
}

// ---------------------------------------------------------------------------

extern "C" void kernel_launch(void* const* d_in, const int* in_sizes, int n_in,
                              void* d_out, int out_size)
{
    const float* hidden = (const float*)d_in[0];   // [B,Q,256]
    const float* enc    = (const float*)d_in[1];   // [B,S,256]
    const float* refp   = (const float*)d_in[2];   // [B,Q,L,2]
    // d_in[3] = spatial_shapes (static, hardcoded)
    const float* off_w  = (const float*)d_in[4];   // [192,256]
    const float* off_b  = (const float*)d_in[5];
    const float* aw_w   = (const float*)d_in[6];   // [96,256]
    const float* aw_b   = (const float*)d_in[7];
    const float* val_w  = (const float*)d_in[8];   // [256,256]
    const float* val_b  = (const float*)d_in[9];
    const float* out_w  = (const float*)d_in[10];  // [256,256]
    const float* out_b  = (const float*)d_in[11];
    float* out = (float*)d_out;

    __half *p_hid_h, *p_enc_h, *p_msda_h, *p_valw, *p_outw, *p_obw;
    float  *p_obb;
    cudaGetSymbolAddress((void**)&p_hid_h,  g_hidden_h);
    cudaGetSymbolAddress((void**)&p_enc_h,  g_enc_h);
    cudaGetSymbolAddress((void**)&p_msda_h, g_msda_h);
    cudaGetSymbolAddress((void**)&p_valw,   g_valw_h);
    cudaGetSymbolAddress((void**)&p_outw,   g_outw_h);
    cudaGetSymbolAddress((void**)&p_obw,    g_obw_h);
    cudaGetSymbolAddress((void**)&p_obb,    g_obb);

    const int MB = MROWS / 128;   // 336
    dim3 blk(256);

    // all fp32 -> fp16 conversions + bias concat in one launch
    f2h_mega<<<(SEG_AWW + 255) / 256, blk>>>(
        (const float4*)hidden, (const float4*)enc,
        (const float4*)val_w, (const float4*)out_w,
        (const float4*)off_w, (const float4*)aw_w,
        off_b, aw_b);

    // merged: value projection (x<4) + fused off/aw projection (x>=4)
    fused_proj_gemm<<<dim3(9, MB), blk>>>(p_enc_h, p_valw, val_b,
                                          p_hid_h, p_obw, p_obb);

    // deformable sampling -> fp16 msda
    msda_sample_kernel<<<MROWS / QB, blk>>>(refp);

    // output projection (fp32 out to d_out)
    out_proj_gemm<<<dim3(4, MB), blk>>>(p_msda_h, p_outw, out_b, out);
}